// round 3
// baseline (speedup 1.0000x reference)
#include <cuda_runtime.h>
#include <cuda_bf16.h>
#include <math.h>

// ---------------------------------------------------------------------------
// Problem constants
// ---------------------------------------------------------------------------
#define NTOK 8192           // 8 * 32 * 32 tokens at stride 32
#define C    768            // channels
#define NE   4              // experts

#define S4_ELEMS  50331648  // 8*96*256*256
#define S8_ELEMS  25165824  // 8*192*128*128
#define S16_ELEMS 12582912  // 8*384*64*64
#define S32_ELEMS 6291456   // 8*768*32*32
#define OFF_S8   50331648
#define OFF_S16  75497472
#define OFF_S32  88080384

// GEMM tiling
#define BM 128
#define BN 64
#define BK 16

// ---------------------------------------------------------------------------
// Scratch (device globals: no allocation allowed)
// ---------------------------------------------------------------------------
__device__ float g_X [NTOK * C];   // tokens [N, C]; reused as Y (expert output) later
__device__ float g_G1[NTOK * C];   // gate hidden
__device__ float g_H [NTOK * C];   // expert hidden (compact, perm order)
__device__ int   g_top[NTOK];
__device__ float g_gv[NTOK];
__device__ int   g_perm[NTOK];     // compact pos -> token id
__device__ int   g_tok2g[NTOK];    // token id -> compact pos
__device__ int   g_counts[NE];
__device__ int   g_offsets[NE + 1];
__device__ int   g_fill[NE];

// ---------------------------------------------------------------------------
// Helpers
// ---------------------------------------------------------------------------
__device__ __forceinline__ float gelu_tanh(float x) {
    // jax.nn.gelu(approximate=True): 0.5*x*(1+tanh(sqrt(2/pi)*(x+0.044715 x^3)))
    float x3 = x * x * x;
    return 0.5f * x * (1.0f + tanhf(0.7978845608028654f * x + 0.035677408136300125f * x3));
}

__device__ __forceinline__ unsigned long long pack2(float x, float y) {
    unsigned long long r;
    asm("mov.b64 %0, {%1, %2};" : "=l"(r) : "f"(x), "f"(y));
    return r;
}
__device__ __forceinline__ void ffma2(unsigned long long& d,
                                      unsigned long long a,
                                      unsigned long long b) {
    asm("fma.rn.f32x2 %0, %1, %2, %3;" : "=l"(d) : "l"(a), "l"(b), "l"(d));
}
__device__ __forceinline__ float2 unpack2(unsigned long long v) {
    float2 r;
    asm("mov.b64 {%0, %1}, %2;" : "=f"(r.x), "=f"(r.y) : "l"(v));
    return r;
}

// ---------------------------------------------------------------------------
// 0. reset counters
// ---------------------------------------------------------------------------
__global__ void init_k() {
    if (threadIdx.x < NE) g_counts[threadIdx.x] = 0;
}

// ---------------------------------------------------------------------------
// 1. BCHW -> [N, C] transpose of s32
// ---------------------------------------------------------------------------
__global__ void transpose_k(const float* __restrict__ s32) {
    __shared__ float tile[32][33];
    int b = blockIdx.z, c0 = blockIdx.y * 32, hw0 = blockIdx.x * 32;
    int tx = threadIdx.x, ty = threadIdx.y;   // (32, 8)
    const float* src = s32 + (b * C + c0) * 1024 + hw0;
    #pragma unroll
    for (int j = 0; j < 32; j += 8)
        tile[ty + j][tx] = src[(ty + j) * 1024 + tx];  // [c_local][hw_local]
    __syncthreads();
    float* dst = g_X + (b * 1024 + hw0) * C + c0;
    #pragma unroll
    for (int j = 0; j < 32; j += 8)
        dst[(ty + j) * C + tx] = tile[tx][ty + j];     // token = ty+j, chan = tx
}

// ---------------------------------------------------------------------------
// 2/6/7. SGEMM with packed f32x2 FMA.
//   MODE 0: G1 = gelu(X @ gate_w1 + b1)                 A=g_X,  Out=g_G1
//   MODE 1: H  = gelu(gather(X, perm) @ exp_w1[e] + b1) A=g_X,  Out=g_H (compact)
//   MODE 2: Y  = (H @ exp_w2[e] + b2) * gate_val        A=g_H,  Out=g_X (compact)
// ---------------------------------------------------------------------------
template <int MODE>
__launch_bounds__(256)
__global__ void gemm_k(const float* __restrict__ Wall,
                       const float* __restrict__ Ball) {
    const int e = (MODE == 0) ? 0 : blockIdx.z;
    int base, cnt;
    if (MODE == 0) { base = 0; cnt = NTOK; }
    else           { base = g_offsets[e]; cnt = g_offsets[e + 1] - base; }

    const int m0 = blockIdx.x * BM;
    if (m0 >= cnt) return;
    const int n0 = blockIdx.y * BN;

    const float* A    = (MODE == 2) ? g_H : g_X;
    float*       Out  = (MODE == 0) ? g_G1 : ((MODE == 1) ? g_H : g_X);
    const float* W    = Wall + ((MODE == 0) ? 0 : e * C * C);
    const float* bias = Ball + ((MODE == 0) ? 0 : e * C);

    __shared__ float As[BK][BM + 4];
    __shared__ float Bs[BK][BN];

    const int tid = threadIdx.x;
    const int tx  = tid & 15;        // N dir (x4)
    const int ty  = tid >> 4;        // M dir (x8)
    const int a_m  = tid >> 2;       // 0..63
    const int a_k4 = (tid & 3) * 4;  // 0/4/8/12
    const int b_k  = tid >> 4;       // 0..15
    const int b_n4 = (tid & 15) * 4; // 0..60

    // Resolve the two A rows this thread loads
    int rows[2];
    #pragma unroll
    for (int i = 0; i < 2; i++) {
        int m = m0 + a_m + i * 64;
        if (m < cnt) {
            if      (MODE == 1) rows[i] = g_perm[base + m];  // gather tokens
            else if (MODE == 2) rows[i] = base + m;          // compact, contiguous
            else                rows[i] = m;
        } else rows[i] = -1;
    }

    unsigned long long acc2[4][4];   // [m-pair][n], each = 2 fp32 accumulators
    #pragma unroll
    for (int p = 0; p < 4; p++)
        #pragma unroll
        for (int j = 0; j < 4; j++) acc2[p][j] = 0ull;

    for (int k0 = 0; k0 < C; k0 += BK) {
        #pragma unroll
        for (int i = 0; i < 2; i++) {
            float4 v = make_float4(0.f, 0.f, 0.f, 0.f);
            if (rows[i] >= 0)
                v = *(const float4*)(A + rows[i] * C + k0 + a_k4);
            As[a_k4 + 0][a_m + i * 64] = v.x;
            As[a_k4 + 1][a_m + i * 64] = v.y;
            As[a_k4 + 2][a_m + i * 64] = v.z;
            As[a_k4 + 3][a_m + i * 64] = v.w;
        }
        *(float4*)&Bs[b_k][b_n4] = *(const float4*)(W + (k0 + b_k) * C + n0 + b_n4);
        __syncthreads();

        #pragma unroll
        for (int kk = 0; kk < BK; kk++) {
            unsigned long long a2[4];
            #pragma unroll
            for (int p = 0; p < 4; p++)
                a2[p] = *(const unsigned long long*)&As[kk][ty * 8 + 2 * p];
            unsigned long long b2[4];
            #pragma unroll
            for (int j = 0; j < 4; j++) {
                float bv = Bs[kk][tx * 4 + j];
                b2[j] = pack2(bv, bv);
            }
            #pragma unroll
            for (int p = 0; p < 4; p++)
                #pragma unroll
                for (int j = 0; j < 4; j++)
                    ffma2(acc2[p][j], a2[p], b2[j]);
        }
        __syncthreads();
    }

    float breg[4];
    #pragma unroll
    for (int j = 0; j < 4; j++) breg[j] = bias[n0 + tx * 4 + j];

    float val[8][4];
    #pragma unroll
    for (int p = 0; p < 4; p++)
        #pragma unroll
        for (int j = 0; j < 4; j++) {
            float2 v = unpack2(acc2[p][j]);
            val[2 * p + 0][j] = v.x;
            val[2 * p + 1][j] = v.y;
        }

    #pragma unroll
    for (int i = 0; i < 8; i++) {
        int m = m0 + ty * 8 + i;
        if (m >= cnt) continue;
        if (MODE == 2) {
            int g = base + m;
            float gv = g_gv[g_perm[g]];
            float4 o;
            o.x = (val[i][0] + breg[0]) * gv;
            o.y = (val[i][1] + breg[1]) * gv;
            o.z = (val[i][2] + breg[2]) * gv;
            o.w = (val[i][3] + breg[3]) * gv;
            *(float4*)(Out + g * C + n0 + tx * 4) = o;
        } else {
            int r = (MODE == 0) ? m : (base + m);
            float4 o;
            o.x = gelu_tanh(val[i][0] + breg[0]);
            o.y = gelu_tanh(val[i][1] + breg[1]);
            o.z = gelu_tanh(val[i][2] + breg[2]);
            o.w = gelu_tanh(val[i][3] + breg[3]);
            *(float4*)(Out + r * C + n0 + tx * 4) = o;
        }
    }
}

// ---------------------------------------------------------------------------
// 3. logits = G1 @ gate_w2 + b2 -> softmax -> top-1 idx + gate value
// ---------------------------------------------------------------------------
__global__ void gate_k(const float* __restrict__ w2, const float* __restrict__ b2) {
    int warp = (blockIdx.x * blockDim.x + threadIdx.x) >> 5;
    int lane = threadIdx.x & 31;
    if (warp >= NTOK) return;
    const float* g = g_G1 + warp * C;
    float l0 = 0.f, l1 = 0.f, l2 = 0.f, l3 = 0.f;
    for (int c = lane; c < C; c += 32) {
        float x = g[c];
        float4 wv = *(const float4*)(w2 + c * 4);
        l0 = fmaf(x, wv.x, l0);
        l1 = fmaf(x, wv.y, l1);
        l2 = fmaf(x, wv.z, l2);
        l3 = fmaf(x, wv.w, l3);
    }
    #pragma unroll
    for (int o = 16; o; o >>= 1) {
        l0 += __shfl_xor_sync(0xffffffffu, l0, o);
        l1 += __shfl_xor_sync(0xffffffffu, l1, o);
        l2 += __shfl_xor_sync(0xffffffffu, l2, o);
        l3 += __shfl_xor_sync(0xffffffffu, l3, o);
    }
    if (lane == 0) {
        l0 += b2[0]; l1 += b2[1]; l2 += b2[2]; l3 += b2[3];
        float m = l0; int idx = 0;
        if (l1 > m) { m = l1; idx = 1; }   // strict '>' keeps first max (jnp.argmax)
        if (l2 > m) { m = l2; idx = 2; }
        if (l3 > m) { m = l3; idx = 3; }
        float s = expf(l0 - m) + expf(l1 - m) + expf(l2 - m) + expf(l3 - m);
        g_top[warp] = idx;
        g_gv[warp]  = 1.0f / s;            // exp(l_top - m) == 1
        atomicAdd(&g_counts[idx], 1);
    }
}

// ---------------------------------------------------------------------------
// 4. tiny exclusive scan + reset fill cursors
// ---------------------------------------------------------------------------
__global__ void scan_k() {
    if (threadIdx.x == 0) {
        int s = 0;
        #pragma unroll
        for (int e = 0; e < NE; e++) {
            g_offsets[e] = s;
            s += g_counts[e];
            g_fill[e] = 0;
        }
        g_offsets[NE] = s;
    }
}

// ---------------------------------------------------------------------------
// 5. build permutation (token -> compact position, grouped by expert)
// ---------------------------------------------------------------------------
__global__ void perm_k() {
    int n = blockIdx.x * blockDim.x + threadIdx.x;
    if (n >= NTOK) return;
    int e = g_top[n];
    int pos = atomicAdd(&g_fill[e], 1);
    int g = g_offsets[e] + pos;
    g_perm[g]   = n;
    g_tok2g[n]  = g;
}

// ---------------------------------------------------------------------------
// 8. coalesced scatter back to BCHW + residual
// ---------------------------------------------------------------------------
__global__ void scatter_k(const float* __restrict__ s32, float* __restrict__ out32) {
    __shared__ float tile[32][33];
    int b = blockIdx.z, c0 = blockIdx.y * 32, hw0 = blockIdx.x * 32;
    int tx = threadIdx.x, ty = threadIdx.y;   // (32, 8)
    // read Y (compact rows via tok2g), coalesced along C
    for (int t = ty; t < 32; t += 8) {
        int n = b * 1024 + hw0 + t;
        int g = g_tok2g[n];
        tile[t][tx] = g_X[g * C + c0 + tx];   // [token_local][c_local]
    }
    __syncthreads();
    int ibase = b * (C * 1024) + hw0;
    #pragma unroll
    for (int j = 0; j < 4; j++) {
        int c = c0 + ty + 8 * j;
        int idx = ibase + c * 1024 + tx;
        out32[idx] = tile[tx][ty + 8 * j] + s32[idx];
    }
}

// ---------------------------------------------------------------------------
// launch
// ---------------------------------------------------------------------------
extern "C" void kernel_launch(void* const* d_in, const int* in_sizes, int n_in,
                              void* d_out, int out_size) {
    const float* s4  = (const float*)d_in[0];
    const float* s8  = (const float*)d_in[1];
    const float* s16 = (const float*)d_in[2];
    const float* s32 = (const float*)d_in[3];
    const float* gw1 = (const float*)d_in[4];
    const float* gb1 = (const float*)d_in[5];
    const float* gw2 = (const float*)d_in[6];
    const float* gb2 = (const float*)d_in[7];
    const float* ew1 = (const float*)d_in[8];
    const float* eb1 = (const float*)d_in[9];
    const float* ew2 = (const float*)d_in[10];
    const float* eb2 = (const float*)d_in[11];
    float* out = (float*)d_out;

    // passthrough copies
    cudaMemcpyAsync(out,            s4,  (size_t)S4_ELEMS  * sizeof(float), cudaMemcpyDeviceToDevice, 0);
    cudaMemcpyAsync(out + OFF_S8,   s8,  (size_t)S8_ELEMS  * sizeof(float), cudaMemcpyDeviceToDevice, 0);
    cudaMemcpyAsync(out + OFF_S16,  s16, (size_t)S16_ELEMS * sizeof(float), cudaMemcpyDeviceToDevice, 0);

    init_k<<<1, 32>>>();
    transpose_k<<<dim3(32, 24, 8), dim3(32, 8)>>>(s32);

    // gate hidden: G1 = gelu(X @ gw1 + gb1)
    gemm_k<0><<<dim3(NTOK / BM, C / BN, 1), 256>>>(gw1, gb1);

    // routing
    gate_k<<<(NTOK * 32) / 256, 256>>>(gw2, gb2);
    scan_k<<<1, 1>>>();
    perm_k<<<NTOK / 256, 256>>>();

    // expert up:   H = gelu(gather(X) @ ew1[e] + eb1[e])
    gemm_k<1><<<dim3(NTOK / BM, C / BN, NE), 256>>>(ew1, eb1);
    // expert down: Y = (H @ ew2[e] + eb2[e]) * gate_val
    gemm_k<2><<<dim3(NTOK / BM, C / BN, NE), 256>>>(ew2, eb2);

    // scatter + residual into out32
    scatter_k<<<dim3(32, 24, 8), dim3(32, 8)>>>(s32, out + OFF_S32);
}

// round 4
// speedup vs baseline: 1.5941x; 1.5941x over previous
#include <cuda_runtime.h>
#include <cuda_bf16.h>
#include <math.h>
#include <stdint.h>

// ---------------------------------------------------------------------------
// Problem constants
// ---------------------------------------------------------------------------
#define NTOK 8192           // 8 * 32 * 32 tokens at stride 32
#define C    768            // channels
#define NE   4              // experts

#define S4_ELEMS  50331648  // 8*96*256*256
#define S8_ELEMS  25165824  // 8*192*128*128
#define S16_ELEMS 12582912  // 8*384*64*64
#define OFF_S8   50331648
#define OFF_S16  75497472
#define OFF_S32  88080384

// GEMM tiling (tf32 mma path)
#define TBM 128
#define TBN 128
#define TBK 16
#define AS_STRIDE 20        // 16 + 4 floats  (conflict-free frag loads)
#define BS_STRIDE 136       // 128 + 8 floats (conflict-free frag loads)
#define AS_BYTES (TBM * AS_STRIDE * 4)   // 10240
#define BS_BYTES (TBK * BS_STRIDE * 4)   // 8704

// ---------------------------------------------------------------------------
// Scratch (device globals: no allocation allowed)
// ---------------------------------------------------------------------------
__device__ float g_X [NTOK * C];   // tokens [N, C]; reused as Y (expert output) later
__device__ float g_G1[NTOK * C];   // gate hidden
__device__ float g_H [NTOK * C];   // expert hidden (compact, perm order)
__device__ int   g_top[NTOK];
__device__ float g_gv[NTOK];
__device__ int   g_perm[NTOK];     // compact pos -> token id
__device__ int   g_tok2g[NTOK];    // token id -> compact pos
__device__ int   g_counts[NE];
__device__ int   g_offsets[NE + 1];
__device__ int   g_fill[NE];

// ---------------------------------------------------------------------------
// Helpers
// ---------------------------------------------------------------------------
__device__ __forceinline__ float gelu_tanh(float x) {
    // jax.nn.gelu(approximate=True)
    float x3 = x * x * x;
    return 0.5f * x * (1.0f + tanhf(0.7978845608028654f * x + 0.035677408136300125f * x3));
}

__device__ __forceinline__ void cp_async16(uint32_t smem_dst, const float* gsrc, bool valid) {
    int sz = valid ? 16 : 0;
    asm volatile("cp.async.cg.shared.global [%0], [%1], 16, %2;\n"
                 :: "r"(smem_dst), "l"(gsrc), "r"(sz));
}
__device__ __forceinline__ void cp_commit() {
    asm volatile("cp.async.commit_group;\n");
}
__device__ __forceinline__ void cp_wait0() {
    asm volatile("cp.async.wait_group 0;\n");
}

__device__ __forceinline__ void mma_tf32(float* c, const uint32_t* a, const uint32_t* b) {
    asm volatile(
        "mma.sync.aligned.m16n8k8.row.col.f32.tf32.tf32.f32 "
        "{%0,%1,%2,%3},{%4,%5,%6,%7},{%8,%9},{%0,%1,%2,%3};\n"
        : "+f"(c[0]), "+f"(c[1]), "+f"(c[2]), "+f"(c[3])
        : "r"(a[0]), "r"(a[1]), "r"(a[2]), "r"(a[3]), "r"(b[0]), "r"(b[1]));
}

// split f into hi (top 10 mantissa bits, exact tf32) + lo (exact remainder)
__device__ __forceinline__ void split_tf32(float f, uint32_t& hi, uint32_t& lo) {
    uint32_t b = __float_as_uint(f);
    hi = b & 0xFFFFE000u;
    float l = f - __uint_as_float(hi);
    lo = __float_as_uint(l);
}

// ---------------------------------------------------------------------------
// 0. reset counters
// ---------------------------------------------------------------------------
__global__ void init_k() {
    if (threadIdx.x < NE) g_counts[threadIdx.x] = 0;
}

// ---------------------------------------------------------------------------
// 1. BCHW -> [N, C] transpose of s32
// ---------------------------------------------------------------------------
__global__ void transpose_k(const float* __restrict__ s32) {
    __shared__ float tile[32][33];
    int b = blockIdx.z, c0 = blockIdx.y * 32, hw0 = blockIdx.x * 32;
    int tx = threadIdx.x, ty = threadIdx.y;   // (32, 8)
    const float* src = s32 + (b * C + c0) * 1024 + hw0;
    #pragma unroll
    for (int j = 0; j < 32; j += 8)
        tile[ty + j][tx] = src[(ty + j) * 1024 + tx];
    __syncthreads();
    float* dst = g_X + (b * 1024 + hw0) * C + c0;
    #pragma unroll
    for (int j = 0; j < 32; j += 8)
        dst[(ty + j) * C + tx] = tile[tx][ty + j];
}

// ---------------------------------------------------------------------------
// tf32 tensor-core GEMM (double-buffered cp.async pipeline)
//   MODE 0 (SPLIT=1): G1 = gelu(X @ gate_w1 + b1)               A=g_X,  Out=g_G1
//   MODE 1 (SPLIT=0): H  = gelu(gather(X,perm) @ ew1[e] + b1)   A=g_X,  Out=g_H
//   MODE 2 (SPLIT=0): Y  = (H @ ew2[e] + b2) * gate_val         A=g_H,  Out=g_X
// Block 128x128, 8 warps (2m x 4n), warp tile 64x32, mma m16n8k8.
// ---------------------------------------------------------------------------
template <int MODE, int SPLIT>
__launch_bounds__(256)
__global__ void mma_gemm_k(const float* __restrict__ Wall,
                           const float* __restrict__ Ball) {
    const int e = (MODE == 0) ? 0 : blockIdx.z;
    int base, cnt;
    if (MODE == 0) { base = 0; cnt = NTOK; }
    else           { base = g_offsets[e]; cnt = g_offsets[e + 1] - base; }

    const int m0 = blockIdx.x * TBM;
    if (m0 >= cnt) return;
    const int n0 = blockIdx.y * TBN;

    const float* A    = (MODE == 2) ? g_H : g_X;
    float*       Out  = (MODE == 0) ? g_G1 : ((MODE == 1) ? g_H : g_X);
    const float* W    = Wall + ((MODE == 0) ? 0 : (size_t)e * C * C);
    const float* bias = Ball + ((MODE == 0) ? 0 : e * C);

    __shared__ __align__(16) float As[2][TBM * AS_STRIDE];  // [m][k]
    __shared__ __align__(16) float Bs[2][TBK * BS_STRIDE];  // [k][n]
    const uint32_t sA = (uint32_t)__cvta_generic_to_shared(&As[0][0]);
    const uint32_t sB = (uint32_t)__cvta_generic_to_shared(&Bs[0][0]);

    const int tid  = threadIdx.x;
    const int wid  = tid >> 5;
    const int lane = tid & 31;
    const int g    = lane >> 2;     // groupID 0..7
    const int tig  = lane & 3;      // threadID in group
    const int mW   = (wid & 1) * 64;
    const int nW   = (wid >> 1) * 32;

    // ---- loader setup: 2 x 16B A chunks + 2 x 16B B chunks per thread/stage
    const float* srcA[2]; uint32_t dstA[2]; bool vA[2];
    #pragma unroll
    for (int i = 0; i < 2; i++) {
        int q   = tid + i * 256;
        int kq  = q >> 7;           // 0..3
        int row = q & 127;          // 0..127
        int m   = m0 + row;
        bool v  = (m < cnt);
        int ar  = 0;
        if (v) {
            if      (MODE == 1) ar = g_perm[base + m];
            else if (MODE == 2) ar = base + m;
            else                ar = m;
        }
        srcA[i] = A + (size_t)ar * C + kq * 4;
        dstA[i] = (uint32_t)(row * AS_STRIDE + kq * 4) * 4u;
        vA[i]   = v;
    }
    const float* srcB[2]; uint32_t dstB[2];
    #pragma unroll
    for (int i = 0; i < 2; i++) {
        int q  = tid + i * 256;
        int k  = q >> 5;            // 0..15
        int n4 = (q & 31) * 4;      // 0..124
        srcB[i] = W + (size_t)k * C + n0 + n4;
        dstB[i] = (uint32_t)(k * BS_STRIDE + n4) * 4u;
    }

    float acc[4][4][4];
    #pragma unroll
    for (int mt = 0; mt < 4; mt++)
        #pragma unroll
        for (int nt = 0; nt < 4; nt++)
            #pragma unroll
            for (int r = 0; r < 4; r++) acc[mt][nt][r] = 0.f;

    const int T = C / TBK;  // 48 stages

    // prologue: stage 0
    #pragma unroll
    for (int i = 0; i < 2; i++) cp_async16(sA + dstA[i], srcA[i], vA[i]);
    #pragma unroll
    for (int i = 0; i < 2; i++) cp_async16(sB + dstB[i], srcB[i], true);
    cp_commit();

    for (int t = 0; t < T; t++) {
        const int cur = t & 1;
        cp_wait0();
        __syncthreads();

        if (t + 1 < T) {
            const int nxt = cur ^ 1;
            const int kf  = (t + 1) * TBK;
            #pragma unroll
            for (int i = 0; i < 2; i++)
                cp_async16(sA + nxt * AS_BYTES + dstA[i], srcA[i] + kf, vA[i]);
            #pragma unroll
            for (int i = 0; i < 2; i++)
                cp_async16(sB + nxt * BS_BYTES + dstB[i], srcB[i] + (size_t)kf * C, true);
            cp_commit();
        }

        const float* Asb = &As[cur][0];
        const float* Bsb = &Bs[cur][0];

        #pragma unroll
        for (int ks = 0; ks < 2; ks++) {
            const int kk = ks * 8;
            uint32_t bh[4][2], bl[4][2];
            #pragma unroll
            for (int nt = 0; nt < 4; nt++) {
                float f0 = Bsb[(kk + tig)     * BS_STRIDE + nW + nt * 8 + g];
                float f1 = Bsb[(kk + tig + 4) * BS_STRIDE + nW + nt * 8 + g];
                if (SPLIT) {
                    split_tf32(f0, bh[nt][0], bl[nt][0]);
                    split_tf32(f1, bh[nt][1], bl[nt][1]);
                } else {
                    bh[nt][0] = __float_as_uint(f0);
                    bh[nt][1] = __float_as_uint(f1);
                }
            }
            #pragma unroll
            for (int mt = 0; mt < 4; mt++) {
                const int r0 = mW + mt * 16 + g;
                float f0 = Asb[ r0      * AS_STRIDE + kk + tig];
                float f1 = Asb[(r0 + 8) * AS_STRIDE + kk + tig];
                float f2 = Asb[ r0      * AS_STRIDE + kk + tig + 4];
                float f3 = Asb[(r0 + 8) * AS_STRIDE + kk + tig + 4];
                uint32_t ah[4], al[4];
                if (SPLIT) {
                    split_tf32(f0, ah[0], al[0]);
                    split_tf32(f1, ah[1], al[1]);
                    split_tf32(f2, ah[2], al[2]);
                    split_tf32(f3, ah[3], al[3]);
                } else {
                    ah[0] = __float_as_uint(f0);
                    ah[1] = __float_as_uint(f1);
                    ah[2] = __float_as_uint(f2);
                    ah[3] = __float_as_uint(f3);
                }
                #pragma unroll
                for (int nt = 0; nt < 4; nt++) {
                    mma_tf32(acc[mt][nt], ah, bh[nt]);
                    if (SPLIT) {
                        mma_tf32(acc[mt][nt], al, bh[nt]);
                        mma_tf32(acc[mt][nt], ah, bl[nt]);
                    }
                }
            }
        }
        __syncthreads();
    }

    // ---- epilogue
    #pragma unroll
    for (int mt = 0; mt < 4; mt++) {
        #pragma unroll
        for (int half = 0; half < 2; half++) {
            const int m = m0 + mW + mt * 16 + g + half * 8;
            if (m >= cnt) continue;
            int drow; float gv = 1.f;
            if (MODE == 0) drow = m;
            else           drow = base + m;
            if (MODE == 2) gv = g_gv[g_perm[base + m]];
            float* orow = Out + (size_t)drow * C;
            #pragma unroll
            for (int nt = 0; nt < 4; nt++) {
                const int col = n0 + nW + nt * 8 + tig * 2;
                float2 bv = *(const float2*)(bias + col);
                float v0 = acc[mt][nt][half * 2 + 0] + bv.x;
                float v1 = acc[mt][nt][half * 2 + 1] + bv.y;
                if (MODE == 2) { v0 *= gv; v1 *= gv; }
                else           { v0 = gelu_tanh(v0); v1 = gelu_tanh(v1); }
                *(float2*)(orow + col) = make_float2(v0, v1);
            }
        }
    }
}

// ---------------------------------------------------------------------------
// 3. logits = G1 @ gate_w2 + b2 -> softmax -> top-1 idx + gate value
// ---------------------------------------------------------------------------
__global__ void gate_k(const float* __restrict__ w2, const float* __restrict__ b2) {
    int warp = (blockIdx.x * blockDim.x + threadIdx.x) >> 5;
    int lane = threadIdx.x & 31;
    if (warp >= NTOK) return;
    const float* g = g_G1 + (size_t)warp * C;
    float l0 = 0.f, l1 = 0.f, l2 = 0.f, l3 = 0.f;
    for (int c = lane; c < C; c += 32) {
        float x = g[c];
        float4 wv = *(const float4*)(w2 + c * 4);
        l0 = fmaf(x, wv.x, l0);
        l1 = fmaf(x, wv.y, l1);
        l2 = fmaf(x, wv.z, l2);
        l3 = fmaf(x, wv.w, l3);
    }
    #pragma unroll
    for (int o = 16; o; o >>= 1) {
        l0 += __shfl_xor_sync(0xffffffffu, l0, o);
        l1 += __shfl_xor_sync(0xffffffffu, l1, o);
        l2 += __shfl_xor_sync(0xffffffffu, l2, o);
        l3 += __shfl_xor_sync(0xffffffffu, l3, o);
    }
    if (lane == 0) {
        l0 += b2[0]; l1 += b2[1]; l2 += b2[2]; l3 += b2[3];
        float m = l0; int idx = 0;
        if (l1 > m) { m = l1; idx = 1; }   // strict '>' keeps first max (jnp.argmax)
        if (l2 > m) { m = l2; idx = 2; }
        if (l3 > m) { m = l3; idx = 3; }
        float s = expf(l0 - m) + expf(l1 - m) + expf(l2 - m) + expf(l3 - m);
        g_top[warp] = idx;
        g_gv[warp]  = 1.0f / s;            // exp(l_top - m) == 1
        atomicAdd(&g_counts[idx], 1);
    }
}

// ---------------------------------------------------------------------------
// 4. tiny exclusive scan + reset fill cursors
// ---------------------------------------------------------------------------
__global__ void scan_k() {
    if (threadIdx.x == 0) {
        int s = 0;
        #pragma unroll
        for (int e = 0; e < NE; e++) {
            g_offsets[e] = s;
            s += g_counts[e];
            g_fill[e] = 0;
        }
        g_offsets[NE] = s;
    }
}

// ---------------------------------------------------------------------------
// 5. build permutation (token -> compact position, grouped by expert)
// ---------------------------------------------------------------------------
__global__ void perm_k() {
    int n = blockIdx.x * blockDim.x + threadIdx.x;
    if (n >= NTOK) return;
    int e = g_top[n];
    int pos = atomicAdd(&g_fill[e], 1);
    int gg = g_offsets[e] + pos;
    g_perm[gg]  = n;
    g_tok2g[n]  = gg;
}

// ---------------------------------------------------------------------------
// 8. coalesced scatter back to BCHW + residual
// ---------------------------------------------------------------------------
__global__ void scatter_k(const float* __restrict__ s32, float* __restrict__ out32) {
    __shared__ float tile[32][33];
    int b = blockIdx.z, c0 = blockIdx.y * 32, hw0 = blockIdx.x * 32;
    int tx = threadIdx.x, ty = threadIdx.y;   // (32, 8)
    for (int t = ty; t < 32; t += 8) {
        int n = b * 1024 + hw0 + t;
        int gg = g_tok2g[n];
        tile[t][tx] = g_X[(size_t)gg * C + c0 + tx];
    }
    __syncthreads();
    int ibase = b * (C * 1024) + hw0;
    #pragma unroll
    for (int j = 0; j < 4; j++) {
        int c = c0 + ty + 8 * j;
        int idx = ibase + c * 1024 + tx;
        out32[idx] = tile[tx][ty + 8 * j] + s32[idx];
    }
}

// ---------------------------------------------------------------------------
// launch
// ---------------------------------------------------------------------------
extern "C" void kernel_launch(void* const* d_in, const int* in_sizes, int n_in,
                              void* d_out, int out_size) {
    const float* s4  = (const float*)d_in[0];
    const float* s8  = (const float*)d_in[1];
    const float* s16 = (const float*)d_in[2];
    const float* s32 = (const float*)d_in[3];
    const float* gw1 = (const float*)d_in[4];
    const float* gb1 = (const float*)d_in[5];
    const float* gw2 = (const float*)d_in[6];
    const float* gb2 = (const float*)d_in[7];
    const float* ew1 = (const float*)d_in[8];
    const float* eb1 = (const float*)d_in[9];
    const float* ew2 = (const float*)d_in[10];
    const float* eb2 = (const float*)d_in[11];
    float* out = (float*)d_out;

    // passthrough copies
    cudaMemcpyAsync(out,           s4,  (size_t)S4_ELEMS  * sizeof(float), cudaMemcpyDeviceToDevice, 0);
    cudaMemcpyAsync(out + OFF_S8,  s8,  (size_t)S8_ELEMS  * sizeof(float), cudaMemcpyDeviceToDevice, 0);
    cudaMemcpyAsync(out + OFF_S16, s16, (size_t)S16_ELEMS * sizeof(float), cudaMemcpyDeviceToDevice, 0);

    init_k<<<1, 32>>>();
    transpose_k<<<dim3(32, 24, 8), dim3(32, 8)>>>(s32);

    // gate hidden: G1 = gelu(X @ gw1 + gb1)   (split-tf32: fp32-accurate)
    mma_gemm_k<0, 1><<<dim3(NTOK / TBM, C / TBN, 1), 256>>>(gw1, gb1);

    // routing
    gate_k<<<(NTOK * 32) / 256, 256>>>(gw2, gb2);
    scan_k<<<1, 1>>>();
    perm_k<<<NTOK / 256, 256>>>();

    // expert up:   H = gelu(gather(X) @ ew1[e] + eb1[e])   (tf32)
    mma_gemm_k<1, 0><<<dim3(NTOK / TBM, C / TBN, NE), 256>>>(ew1, eb1);
    // expert down: Y = (H @ ew2[e] + eb2[e]) * gate_val    (tf32)
    mma_gemm_k<2, 0><<<dim3(NTOK / TBM, C / TBN, NE), 256>>>(ew2, eb2);

    // scatter + residual into out32
    scatter_k<<<dim3(32, 24, 8), dim3(32, 8)>>>(s32, out + OFF_S32);
}